// round 1
// baseline (speedup 1.0000x reference)
#include <cuda_runtime.h>
#include <cuda_bf16.h>
#include <cstdint>

// OHEM smooth-L1 loss.
// y_pred, y_true: [64, 262144] fp32. Output: scalar fp32.
// neg set per row = top-k of |yp-yt| among (yt==0) elements, k = min(2*num_pos, N-1).
// Selected exactly via 3-level radix select on float bits (11/11/10).

static constexpr int B = 64;
static constexpr int N = 256 * 256 * 4;     // 262144
static constexpr int L1_BINS = 2048;        // top 11 bits of float bits
static constexpr int NEG_POS = 2;

// ---------------- device scratch (zeroed each launch via one memset) ----------
struct Accum {
    unsigned hist_cnt[B][L1_BINS];   // level-1 count
    float    hist_sum[B][L1_BINS];   // level-1 sum of smooth_l1(a)
    unsigned pos_cnt[B];
    double   pos_sum[B];
    unsigned cand_cnt[B];
};
__device__ Accum g_acc;

// not zeroed (written unconditionally)
__device__ unsigned g_cand[B][N];    // candidate keys (worst case: whole row in one bin)
__device__ int      g_b1[B];
__device__ unsigned g_cab1[B];       // count strictly above bin b1
__device__ double   g_sab1[B];       // f-sum strictly above bin b1
__device__ int      g_k[B];
__device__ double   g_neg_sum[B];

__device__ __forceinline__ float smooth_l1(float a) {
    return a < 1.f ? 0.5f * a * a : a - 0.5f;
}

__device__ double block_reduce_double(double v) {
    __shared__ double sh[32];
    int lane = threadIdx.x & 31, w = threadIdx.x >> 5;
    #pragma unroll
    for (int o = 16; o; o >>= 1) v += __shfl_down_sync(0xffffffffu, v, o);
    __syncthreads();
    if (lane == 0) sh[w] = v;
    __syncthreads();
    double r = 0.0;
    if (w == 0) {
        int nw = (blockDim.x + 31) >> 5;
        r = (lane < nw) ? sh[lane] : 0.0;
        #pragma unroll
        for (int o = 16; o; o >>= 1) r += __shfl_down_sync(0xffffffffu, r, o);
    }
    return r;   // valid in thread 0
}

// ---------------- Pass A: pos stats + level-1 histogram ----------------------
static constexpr int TPB_A = 256;
static constexpr int VEC = 4;
static constexpr int ITERS_A = 4;                       // 4096 elems / block
static constexpr int EPB = TPB_A * VEC * ITERS_A;       // 4096
static constexpr int BLK_PER_ROW = N / EPB;             // 64

__global__ void __launch_bounds__(TPB_A) pass_a(const float* __restrict__ yp,
                                                const float* __restrict__ yt) {
    __shared__ unsigned s_cnt[L1_BINS];
    __shared__ float    s_sum[L1_BINS];
    const int r = blockIdx.y;
    for (int i = threadIdx.x; i < L1_BINS; i += TPB_A) { s_cnt[i] = 0u; s_sum[i] = 0.f; }
    __syncthreads();

    const long rowbase = (long)r * N + (long)blockIdx.x * EPB;
    float psum = 0.f; int pcnt = 0;
    #pragma unroll
    for (int it = 0; it < ITERS_A; it++) {
        long idx = rowbase + it * (TPB_A * VEC) + threadIdx.x * VEC;
        float4 p = *reinterpret_cast<const float4*>(yp + idx);
        float4 t = *reinterpret_cast<const float4*>(yt + idx);
        float pv[4] = {p.x, p.y, p.z, p.w};
        float tv[4] = {t.x, t.y, t.z, t.w};
        #pragma unroll
        for (int j = 0; j < 4; j++) {
            float d = pv[j] - tv[j];
            float a = fabsf(d);
            float el = smooth_l1(a);
            if (tv[j] != 0.f) { pcnt++; psum += el; }
            else {
                unsigned key = __float_as_uint(a);
                unsigned b = key >> 21;
                atomicAdd(&s_cnt[b], 1u);
                atomicAdd(&s_sum[b], el);
            }
        }
    }
    __syncthreads();
    for (int i = threadIdx.x; i < L1_BINS; i += TPB_A) {
        if (s_cnt[i]) {
            atomicAdd(&g_acc.hist_cnt[r][i], s_cnt[i]);
            atomicAdd(&g_acc.hist_sum[r][i], s_sum[i]);
        }
    }
    // pos reduce: warp-level then atomic
    #pragma unroll
    for (int o = 16; o; o >>= 1) {
        psum += __shfl_down_sync(0xffffffffu, psum, o);
        pcnt += __shfl_down_sync(0xffffffffu, pcnt, o);
    }
    if ((threadIdx.x & 31) == 0 && pcnt) {
        atomicAdd(&g_acc.pos_cnt[r], (unsigned)pcnt);
        atomicAdd(&g_acc.pos_sum[r], (double)psum);
    }
}

// ---------------- Pass B: find level-1 threshold bin per row -----------------
__global__ void __launch_bounds__(256) pass_b() {
    const int r = blockIdx.x;
    const int tid = threadIdx.x;
    const unsigned np = g_acc.pos_cnt[r];
    unsigned k = 2u * np; if (k > (unsigned)(N - 1)) k = (unsigned)(N - 1);

    __shared__ unsigned chunk[256];
    unsigned c = 0;
    #pragma unroll
    for (int j = 0; j < 8; j++) c += g_acc.hist_cnt[r][tid * 8 + j];
    chunk[tid] = c;
    __syncthreads();

    __shared__ int sb1; __shared__ unsigned scab;
    if (tid == 0) {
        g_k[r] = (int)k;
        int b1 = -1; unsigned cab = 0;
        if (k > 0) {
            unsigned suf = 0; int ch = 0;
            for (int i = 255; i >= 0; i--) {
                if (suf + chunk[i] >= k) { ch = i; break; }
                suf += chunk[i];
                if (i == 0) ch = 0;
            }
            int bf = ch * 8;
            for (int b = ch * 8 + 7; b >= ch * 8; b--) {
                unsigned cb = g_acc.hist_cnt[r][b];
                if (suf + cb >= k) { bf = b; break; }
                suf += cb;
            }
            b1 = bf; cab = suf;
        }
        sb1 = b1; scab = cab;
    }
    __syncthreads();
    const int b1 = sb1;
    double ds = 0.0;
    if (b1 >= 0)
        for (int b = b1 + 1 + tid; b < L1_BINS; b += 256) ds += (double)g_acc.hist_sum[r][b];
    ds = block_reduce_double(ds);
    if (tid == 0) { g_b1[r] = b1; g_cab1[r] = scab; g_sab1[r] = ds; }
}

// ---------------- Pass C: compact candidates in threshold bin ----------------
__global__ void __launch_bounds__(TPB_A) pass_c(const float* __restrict__ yp,
                                                const float* __restrict__ yt) {
    __shared__ unsigned s_keys[EPB];
    __shared__ unsigned s_n, s_base;
    const int r = blockIdx.y;
    const int b1 = g_b1[r];
    if (threadIdx.x == 0) s_n = 0u;
    __syncthreads();

    if (b1 >= 0) {
        const long rowbase = (long)r * N + (long)blockIdx.x * EPB;
        #pragma unroll
        for (int it = 0; it < ITERS_A; it++) {
            long idx = rowbase + it * (TPB_A * VEC) + threadIdx.x * VEC;
            float4 p = *reinterpret_cast<const float4*>(yp + idx);
            float4 t = *reinterpret_cast<const float4*>(yt + idx);
            float pv[4] = {p.x, p.y, p.z, p.w};
            float tv[4] = {t.x, t.y, t.z, t.w};
            #pragma unroll
            for (int j = 0; j < 4; j++) {
                if (tv[j] == 0.f) {
                    unsigned key = __float_as_uint(fabsf(pv[j]));
                    if ((int)(key >> 21) == b1) {
                        unsigned slot = atomicAdd(&s_n, 1u);
                        s_keys[slot] = key;
                    }
                }
            }
        }
    }
    __syncthreads();
    if (threadIdx.x == 0 && s_n) s_base = atomicAdd(&g_acc.cand_cnt[r], s_n);
    __syncthreads();
    for (unsigned i = threadIdx.x; i < s_n; i += TPB_A) g_cand[r][s_base + i] = s_keys[i];
}

// ---------------- Pass E: 2-level refine over candidates ---------------------
__global__ void __launch_bounds__(512) pass_e() {
    const int r = blockIdx.x;
    const int tid = threadIdx.x;
    __shared__ unsigned h_cnt[2048];
    __shared__ float    h_sum[2048];
    __shared__ unsigned s_chunk[512];
    __shared__ int s_b; __shared__ unsigned s_c;
    __shared__ double s_s2;

    const int k = g_k[r];
    if (k <= 0) { if (tid == 0) g_neg_sum[r] = 0.0; return; }
    const unsigned m = g_acc.cand_cnt[r];
    const unsigned kc = (unsigned)k - g_cab1[r];   // needed within candidates, >= 1

    // ---- level 2: bits [20:10] ----
    for (int i = tid; i < 2048; i += 512) { h_cnt[i] = 0u; h_sum[i] = 0.f; }
    __syncthreads();
    for (unsigned i = tid; i < m; i += 512) {
        unsigned key = g_cand[r][i];
        unsigned b = (key >> 10) & 0x7FFu;
        float f = smooth_l1(__uint_as_float(key));
        atomicAdd(&h_cnt[b], 1u);
        atomicAdd(&h_sum[b], f);
    }
    __syncthreads();
    { unsigned cc = 0;
      #pragma unroll
      for (int j = 0; j < 4; j++) cc += h_cnt[tid * 4 + j];
      s_chunk[tid] = cc; }
    __syncthreads();
    if (tid == 0) {
        unsigned suf = 0; int ch = 0;
        for (int i = 511; i >= 0; i--) {
            if (suf + s_chunk[i] >= kc) { ch = i; break; }
            suf += s_chunk[i];
            if (i == 0) ch = 0;
        }
        int bf = ch * 4;
        for (int b = ch * 4 + 3; b >= ch * 4; b--) {
            unsigned cb = h_cnt[b];
            if (suf + cb >= kc) { bf = b; break; }
            suf += cb;
        }
        s_b = bf; s_c = suf;
    }
    __syncthreads();
    const int b2 = s_b;
    const unsigned c2 = s_c;
    double s2 = 0.0;
    for (int b = b2 + 1 + tid; b < 2048; b += 512) s2 += (double)h_sum[b];
    s2 = block_reduce_double(s2);
    if (tid == 0) s_s2 = s2;
    const unsigned kc2 = kc - c2;
    __syncthreads();

    // ---- level 3: bits [9:0] ----
    for (int i = tid; i < 1024; i += 512) { h_cnt[i] = 0u; h_sum[i] = 0.f; }
    __syncthreads();
    for (unsigned i = tid; i < m; i += 512) {
        unsigned key = g_cand[r][i];
        if (((key >> 10) & 0x7FFu) == (unsigned)b2) {
            unsigned b = key & 0x3FFu;
            atomicAdd(&h_cnt[b], 1u);
            atomicAdd(&h_sum[b], smooth_l1(__uint_as_float(key)));
        }
    }
    __syncthreads();
    if (tid < 512) {
        unsigned cc = h_cnt[tid * 2] + h_cnt[tid * 2 + 1];
        s_chunk[tid] = cc;
    }
    __syncthreads();
    if (tid == 0) {
        unsigned suf = 0; int ch = 0;
        for (int i = 511; i >= 0; i--) {
            if (suf + s_chunk[i] >= kc2) { ch = i; break; }
            suf += s_chunk[i];
            if (i == 0) ch = 0;
        }
        int bf = ch * 2;
        for (int b = ch * 2 + 1; b >= ch * 2; b--) {
            unsigned cb = h_cnt[b];
            if (suf + cb >= kc2) { bf = b; break; }
            suf += cb;
        }
        s_b = bf; s_c = suf;
    }
    __syncthreads();
    const int b3 = s_b;
    const unsigned c3 = s_c;
    double s3 = 0.0;
    for (int b = b3 + 1 + tid; b < 1024; b += 512) s3 += (double)h_sum[b];
    s3 = block_reduce_double(s3);
    if (tid == 0) {
        unsigned eq = kc2 - c3;   // tied elements needed at exact threshold bits
        unsigned thr = ((unsigned)g_b1[r] << 21) | ((unsigned)b2 << 10) | (unsigned)b3;
        float fT = smooth_l1(__uint_as_float(thr));
        g_neg_sum[r] = g_sab1[r] + s_s2 + s3 + (double)eq * (double)fT;
    }
}

// ---------------- Pass F: final scalar ---------------------------------------
__global__ void pass_f(float* __restrict__ out) {
    __shared__ double a[B], b[B], c[B], d[B];
    int tid = threadIdx.x;   // B threads
    a[tid] = g_acc.pos_sum[tid];
    b[tid] = (double)g_acc.pos_cnt[tid];
    c[tid] = g_neg_sum[tid];
    d[tid] = (double)g_k[tid];
    __syncthreads();
    if (tid == 0) {
        double PS = 0, PC = 0, NS = 0, NC = 0;
        for (int i = 0; i < B; i++) { PS += a[i]; PC += b[i]; NS += c[i]; NC += d[i]; }
        double pos_loss = (PC > 0.0) ? PS / PC : 0.0;
        double neg_loss = (NC > 0.0) ? NS / NC : 0.0;
        out[0] = (float)((double)NEG_POS * pos_loss + neg_loss);
    }
}

// ---------------- launch ------------------------------------------------------
extern "C" void kernel_launch(void* const* d_in, const int* in_sizes, int n_in,
                              void* d_out, int out_size) {
    const float* yp = (const float*)d_in[0];
    const float* yt = (const float*)d_in[1];
    float* out = (float*)d_out;

    void* accPtr = nullptr;
    cudaGetSymbolAddress(&accPtr, g_acc);
    cudaMemsetAsync(accPtr, 0, sizeof(Accum));

    dim3 grid(BLK_PER_ROW, B);
    pass_a<<<grid, TPB_A>>>(yp, yt);
    pass_b<<<B, 256>>>();
    pass_c<<<grid, TPB_A>>>(yp, yt);
    pass_e<<<B, 512>>>();
    pass_f<<<1, B>>>(out);
}

// round 2
// speedup vs baseline: 1.2910x; 1.2910x over previous
#include <cuda_runtime.h>
#include <cuda_bf16.h>
#include <cstdint>

// OHEM smooth-L1 loss. y_pred,y_true: [64, 262144] fp32 -> scalar fp32.
// Exact top-k hard-negative selection via counts-only radix select:
//   pass A: pos stats + 1024-bin (top 11 float bits) count histogram (match_any-aggregated)
//   pass B: per-row level-1 threshold bin b1 (parallel suffix scan)
//   pass C: collect keys with bin >= b1 (warp-aggregated append)
//   pass E: exact 3-level refine + neg sum over candidates (1 block/row, 1024 thr)
//   pass F: final scalar

static constexpr int B = 64;
static constexpr int N = 256 * 256 * 4;   // 262144
static constexpr int NB1 = 1024;          // key >> 21 (sign bit is 0)
static constexpr int NEG_POS = 2;

struct Accum {
    unsigned hist[B][NB1];
    unsigned pos_cnt[B];
    double   pos_sum[B];
    unsigned cand_cnt[B];
};
__device__ Accum g_acc;                    // zeroed via one small memset
__device__ unsigned g_cand[B][N];          // candidate keys (worst-case safe)
__device__ int      g_b1[B];
__device__ unsigned g_cab[B];              // count strictly above bin b1
__device__ int      g_k[B];
__device__ double   g_neg[B];

__device__ __forceinline__ float fsl1(float a) { return a < 1.f ? 0.5f * a * a : a - 0.5f; }

// valid in thread 0 only; safe for back-to-back calls (full barriers inside)
__device__ double block_reduce_double(double v) {
    __shared__ double sh[32];
    int lane = threadIdx.x & 31, w = threadIdx.x >> 5;
    #pragma unroll
    for (int o = 16; o; o >>= 1) v += __shfl_down_sync(0xffffffffu, v, o);
    __syncthreads();
    if (lane == 0) sh[w] = v;
    __syncthreads();
    double r = 0.0;
    if (w == 0) {
        int nw = (blockDim.x + 31) >> 5;
        r = (lane < nw) ? sh[lane] : 0.0;
        #pragma unroll
        for (int o = 16; o; o >>= 1) r += __shfl_down_sync(0xffffffffu, r, o);
    }
    return r;
}

// ---------------- Pass A ------------------------------------------------------
static constexpr int TPB = 256;
static constexpr int VEC = 4;
static constexpr int ITERS = 4;
static constexpr int EPB = TPB * VEC * ITERS;   // 4096
static constexpr int BPR = N / EPB;             // 64

__global__ void __launch_bounds__(TPB) pass_a(const float* __restrict__ yp,
                                              const float* __restrict__ yt) {
    __shared__ unsigned s_cnt[NB1];
    const int r = blockIdx.y;
    for (int i = threadIdx.x; i < NB1; i += TPB) s_cnt[i] = 0u;
    __syncthreads();

    const size_t base = (size_t)r * N + (size_t)blockIdx.x * EPB;
    const unsigned lane = threadIdx.x & 31u;
    double psum = 0.0; int pcnt = 0;
    #pragma unroll
    for (int it = 0; it < ITERS; it++) {
        size_t idx = base + (size_t)it * (TPB * VEC) + (size_t)threadIdx.x * VEC;
        float4 p = *reinterpret_cast<const float4*>(yp + idx);
        float4 t = *reinterpret_cast<const float4*>(yt + idx);
        float pv[4] = {p.x, p.y, p.z, p.w};
        float tv[4] = {t.x, t.y, t.z, t.w};
        #pragma unroll
        for (int j = 0; j < 4; j++) {
            float a = fabsf(pv[j] - tv[j]);
            bool neg = (tv[j] == 0.f);
            unsigned nm = __ballot_sync(0xffffffffu, neg);
            if (!neg) { pcnt++; psum += (double)fsl1(a); }
            if (neg) {
                unsigned b = __float_as_uint(a) >> 21;   // a == |pv| here
                unsigned mm = __match_any_sync(nm, b);
                if ((mm & ((1u << lane) - 1u)) == 0u)    // leader of match group
                    atomicAdd(&s_cnt[b], (unsigned)__popc(mm));
            }
        }
    }
    __syncthreads();
    for (int i = threadIdx.x; i < NB1; i += TPB)
        if (s_cnt[i]) atomicAdd(&g_acc.hist[r][i], s_cnt[i]);

    #pragma unroll
    for (int o = 16; o; o >>= 1) {
        psum += __shfl_down_sync(0xffffffffu, psum, o);
        pcnt += __shfl_down_sync(0xffffffffu, pcnt, o);
    }
    if (lane == 0 && pcnt) {
        atomicAdd(&g_acc.pos_cnt[r], (unsigned)pcnt);
        atomicAdd(&g_acc.pos_sum[r], psum);
    }
}

// ---------------- Pass B: level-1 threshold -----------------------------------
__global__ void __launch_bounds__(256) pass_b() {
    const int r = blockIdx.x, tid = threadIdx.x;
    __shared__ unsigned h[NB1];
    __shared__ unsigned sfx[256];
    __shared__ int sb; __shared__ unsigned sc;
    for (int i = tid; i < NB1; i += 256) h[i] = g_acc.hist[r][i];
    __syncthreads();
    unsigned cs = 0;
    #pragma unroll
    for (int j = 0; j < 4; j++) cs += h[tid * 4 + j];
    sfx[tid] = cs;
    __syncthreads();
    for (int off = 1; off < 256; off <<= 1) {            // inclusive suffix scan
        unsigned v = (tid + off < 256) ? sfx[tid + off] : 0u;
        __syncthreads();
        sfx[tid] += v;
        __syncthreads();
    }
    unsigned np = g_acc.pos_cnt[r];
    unsigned k = 2u * np; if (k > (unsigned)(N - 1)) k = (unsigned)(N - 1);
    if (tid == 0) { sb = -1; sc = 0u; g_k[r] = (int)k; }
    __syncthreads();
    unsigned total = sfx[0];
    unsigned keff = (k > total) ? total : k;
    if (keff > 0) {
        unsigned si = sfx[tid];
        unsigned snext = (tid < 255) ? sfx[tid + 1] : 0u;
        if (si >= keff && snext < keff) {
            unsigned suf = snext;
            for (int b = tid * 4 + 3; b >= tid * 4; b--) {
                if (suf + h[b] >= keff) { sb = b; sc = suf; break; }
                suf += h[b];
            }
        }
    }
    __syncthreads();
    if (tid == 0) { g_b1[r] = sb; g_cab[r] = sc; }
}

// ---------------- Pass C: collect candidates (bin >= b1) ----------------------
__global__ void __launch_bounds__(TPB) pass_c(const float* __restrict__ yp,
                                              const float* __restrict__ yt) {
    __shared__ unsigned s_keys[EPB];
    __shared__ unsigned s_n, s_base;
    const int r = blockIdx.y;
    const int b1 = g_b1[r];
    const unsigned lane = threadIdx.x & 31u;
    if (threadIdx.x == 0) s_n = 0u;
    __syncthreads();

    if (b1 >= 0) {
        const size_t base = (size_t)r * N + (size_t)blockIdx.x * EPB;
        #pragma unroll
        for (int it = 0; it < ITERS; it++) {
            size_t idx = base + (size_t)it * (TPB * VEC) + (size_t)threadIdx.x * VEC;
            float4 p = *reinterpret_cast<const float4*>(yp + idx);
            float4 t = *reinterpret_cast<const float4*>(yt + idx);
            float pv[4] = {p.x, p.y, p.z, p.w};
            float tv[4] = {t.x, t.y, t.z, t.w};
            #pragma unroll
            for (int j = 0; j < 4; j++) {
                unsigned key = __float_as_uint(fabsf(pv[j]));
                bool take = (tv[j] == 0.f) && ((int)(key >> 21) >= b1);
                unsigned bm = __ballot_sync(0xffffffffu, take);
                if (take) {
                    unsigned leader = __ffs(bm) - 1u;
                    unsigned pre = __popc(bm & ((1u << lane) - 1u));
                    unsigned wbase;
                    if (lane == leader) wbase = atomicAdd(&s_n, (unsigned)__popc(bm));
                    wbase = __shfl_sync(bm, wbase, leader);
                    s_keys[wbase + pre] = key;
                }
            }
        }
    }
    __syncthreads();
    if (threadIdx.x == 0 && s_n) s_base = atomicAdd(&g_acc.cand_cnt[r], s_n);
    __syncthreads();
    for (unsigned i = threadIdx.x; i < s_n; i += TPB) g_cand[r][s_base + i] = s_keys[i];
}

// ---------------- Pass E: exact refine + neg sum ------------------------------
__global__ void __launch_bounds__(1024) pass_e() {
    const int r = blockIdx.x, tid = threadIdx.x;
    __shared__ unsigned h2[2048];
    __shared__ unsigned h3c[1024];
    __shared__ float    h3s[1024];
    __shared__ unsigned sfx[1024];
    __shared__ int sb; __shared__ unsigned sc;
    __shared__ double d_sA, d_s2;

    const int k = g_k[r];
    const int b1 = g_b1[r];
    if (b1 < 0 || k <= 0) { if (tid == 0) g_neg[r] = 0.0; return; }
    const unsigned m = g_acc.cand_cnt[r];
    const unsigned cab = g_cab[r];
    const unsigned* cand = g_cand[r];

    for (int i = tid; i < 2048; i += 1024) h2[i] = 0u;
    h3c[tid] = 0u; h3s[tid] = 0.f;
    __syncthreads();

    // pass 1 over candidates: sum of surely-selected + level-2 hist of threshold bin
    double sA = 0.0;
    for (unsigned i = tid; i < m; i += 1024) {
        unsigned key = cand[i];
        if ((int)(key >> 21) > b1) sA += (double)fsl1(__uint_as_float(key));
        else atomicAdd(&h2[(key >> 10) & 0x7FFu], 1u);
    }
    sA = block_reduce_double(sA);
    if (tid == 0) d_sA = sA;
    __syncthreads();

    // level-2 threshold (bits [20:10])
    unsigned cs = h2[tid * 2] + h2[tid * 2 + 1];
    sfx[tid] = cs;
    __syncthreads();
    for (int off = 1; off < 1024; off <<= 1) {
        unsigned v = (tid + off < 1024) ? sfx[tid + off] : 0u;
        __syncthreads();
        sfx[tid] += v;
        __syncthreads();
    }
    unsigned tot2 = sfx[0];
    unsigned kc = (unsigned)k - cab;
    if (kc > tot2) kc = tot2;
    if (tid == 0) { sb = 0; sc = 0u; }
    __syncthreads();
    {
        unsigned si = sfx[tid];
        unsigned snext = (tid < 1023) ? sfx[tid + 1] : 0u;
        if (si >= kc && snext < kc) {
            unsigned suf = snext;
            for (int b = tid * 2 + 1; b >= tid * 2; b--) {
                if (suf + h2[b] >= kc) { sb = b; sc = suf; break; }
                suf += h2[b];
            }
        }
    }
    __syncthreads();
    const int b2 = sb;
    const unsigned c2 = sc;
    const unsigned kc2 = kc - c2;
    __syncthreads();

    // pass 2 over candidates: sum mid>b2, level-3 hist (cnt + f32 sum) of mid==b2
    double s2 = 0.0;
    for (unsigned i = tid; i < m; i += 1024) {
        unsigned key = cand[i];
        if ((int)(key >> 21) == b1) {
            unsigned mid = (key >> 10) & 0x7FFu;
            if ((int)mid > b2) s2 += (double)fsl1(__uint_as_float(key));
            else if ((int)mid == b2) {
                unsigned lo = key & 0x3FFu;
                atomicAdd(&h3c[lo], 1u);
                atomicAdd(&h3s[lo], fsl1(__uint_as_float(key)));
            }
        }
    }
    s2 = block_reduce_double(s2);
    if (tid == 0) d_s2 = s2;
    __syncthreads();

    // level-3 threshold (bits [9:0])
    sfx[tid] = h3c[tid];
    __syncthreads();
    for (int off = 1; off < 1024; off <<= 1) {
        unsigned v = (tid + off < 1024) ? sfx[tid + off] : 0u;
        __syncthreads();
        sfx[tid] += v;
        __syncthreads();
    }
    unsigned tot3 = sfx[0];
    unsigned kc3 = (kc2 > tot3) ? tot3 : kc2;
    if (tid == 0) { sb = 0; sc = 0u; }
    __syncthreads();
    {
        unsigned si = sfx[tid];
        unsigned snext = (tid < 1023) ? sfx[tid + 1] : 0u;
        if (si >= kc3 && snext < kc3) { sb = tid; sc = snext; }
    }
    __syncthreads();
    const int b3 = sb;
    const unsigned c3 = sc;
    double s3 = (tid > b3) ? (double)h3s[tid] : 0.0;
    s3 = block_reduce_double(s3);
    if (tid == 0) {
        unsigned eq = kc3 - c3;   // tied elements at exact threshold bits
        unsigned thr = ((unsigned)b1 << 21) | ((unsigned)b2 << 10) | (unsigned)b3;
        float fT = fsl1(__uint_as_float(thr));
        g_neg[r] = d_sA + d_s2 + s3 + (double)eq * (double)fT;
    }
}

// ---------------- Pass F ------------------------------------------------------
__global__ void pass_f(float* __restrict__ out) {
    __shared__ double a[B], b[B], c[B], d[B];
    int tid = threadIdx.x;   // B threads
    a[tid] = g_acc.pos_sum[tid];
    b[tid] = (double)g_acc.pos_cnt[tid];
    c[tid] = g_neg[tid];
    d[tid] = (double)g_k[tid];
    __syncthreads();
    if (tid == 0) {
        double PS = 0, PC = 0, NS = 0, NC = 0;
        for (int i = 0; i < B; i++) { PS += a[i]; PC += b[i]; NS += c[i]; NC += d[i]; }
        double pos_loss = (PC > 0.0) ? PS / PC : 0.0;
        double neg_loss = (NC > 0.0) ? NS / NC : 0.0;
        out[0] = (float)((double)NEG_POS * pos_loss + neg_loss);
    }
}

// ---------------- launch ------------------------------------------------------
extern "C" void kernel_launch(void* const* d_in, const int* in_sizes, int n_in,
                              void* d_out, int out_size) {
    const float* yp = (const float*)d_in[0];
    const float* yt = (const float*)d_in[1];
    float* out = (float*)d_out;

    void* accPtr = nullptr;
    cudaGetSymbolAddress(&accPtr, g_acc);
    cudaMemsetAsync(accPtr, 0, sizeof(Accum));

    dim3 grid(BPR, B);
    pass_a<<<grid, TPB>>>(yp, yt);
    pass_b<<<B, 256>>>();
    pass_c<<<grid, TPB>>>(yp, yt);
    pass_e<<<B, 1024>>>();
    pass_f<<<1, B>>>(out);
}

// round 3
// speedup vs baseline: 1.7198x; 1.3321x over previous
#include <cuda_runtime.h>
#include <cuda_bf16.h>
#include <cstdint>

// OHEM smooth-L1 loss. y_pred,y_true: [64, 262144] fp32 -> scalar fp32.
//  pass A : single sweep. pos stats + append neg keys with |d| >= 1.25 (cand).
//  pass FB: fallback (no-op unless cand_cnt < k): append remaining neg keys.
//  pass E : exact 3-level radix select + neg sum over L2-resident candidates.
//  pass F : final scalar.

static constexpr int B = 64;
static constexpr int N = 256 * 256 * 4;        // 262144
static constexpr int NEG_POS = 2;
static constexpr unsigned CUT_BITS = 0x3FA00000u;   // 1.25f

struct Zeroed {
    unsigned cand_cnt[B];
    unsigned fb_cnt[B];
    unsigned pos_cnt[B];
    double   pos_sum[B];
};
__device__ Zeroed g_z;                 // 1.3 KB memset per launch
__device__ unsigned g_cand[B][N];      // worst-case safe
__device__ double   g_neg[B];

__device__ __forceinline__ float fsl1(float a) { return a < 1.f ? 0.5f * a * a : a - 0.5f; }
__device__ __forceinline__ unsigned kmin(unsigned pc) {
    unsigned k = 2u * pc; return k > (unsigned)(N - 1) ? (unsigned)(N - 1) : k;
}

// valid in thread 0; internally barriered
__device__ double block_reduce_double(double v) {
    __shared__ double sh[32];
    int lane = threadIdx.x & 31, w = threadIdx.x >> 5;
    #pragma unroll
    for (int o = 16; o; o >>= 1) v += __shfl_down_sync(0xffffffffu, v, o);
    __syncthreads();
    if (lane == 0) sh[w] = v;
    __syncthreads();
    double r = 0.0;
    if (w == 0) {
        int nw = (blockDim.x + 31) >> 5;
        r = (lane < nw) ? sh[lane] : 0.0;
        #pragma unroll
        for (int o = 16; o; o >>= 1) r += __shfl_down_sync(0xffffffffu, r, o);
    }
    return r;
}

// ---------------- Pass A: single data sweep ----------------------------------
static constexpr int TPB = 256;
static constexpr int VEC = 4;
static constexpr int ITERS = 4;
static constexpr int EPB = TPB * VEC * ITERS;   // 4096
static constexpr int BPR = N / EPB;             // 64

__global__ void __launch_bounds__(TPB) pass_a(const float* __restrict__ yp,
                                              const float* __restrict__ yt) {
    __shared__ unsigned s_keys[EPB];
    __shared__ unsigned s_n, s_base;
    const int r = blockIdx.y;
    const unsigned lane = threadIdx.x & 31u;
    if (threadIdx.x == 0) s_n = 0u;
    __syncthreads();

    const size_t base = (size_t)r * N + (size_t)blockIdx.x * EPB;
    double psum = 0.0; int pcnt = 0;
    #pragma unroll
    for (int it = 0; it < ITERS; it++) {
        size_t idx = base + (size_t)it * (TPB * VEC) + (size_t)threadIdx.x * VEC;
        float4 p = *reinterpret_cast<const float4*>(yp + idx);
        float4 t = *reinterpret_cast<const float4*>(yt + idx);
        float pv[4] = {p.x, p.y, p.z, p.w};
        float tv[4] = {t.x, t.y, t.z, t.w};
        #pragma unroll
        for (int j = 0; j < 4; j++) {
            float a = fabsf(pv[j] - tv[j]);          // for neg (tv==0) this is |pv|
            unsigned key = __float_as_uint(a);
            bool pos = (tv[j] != 0.f);
            if (pos) { pcnt++; psum += (double)fsl1(a); }
            bool take = !pos && (key >= CUT_BITS);
            unsigned bm = __ballot_sync(0xffffffffu, take);
            if (take) {
                unsigned leader = __ffs(bm) - 1u;
                unsigned pre = __popc(bm & ((1u << lane) - 1u));
                unsigned wbase;
                if (lane == leader) wbase = atomicAdd(&s_n, (unsigned)__popc(bm));
                wbase = __shfl_sync(bm, wbase, leader);
                s_keys[wbase + pre] = key;
            }
        }
    }
    __syncthreads();
    if (threadIdx.x == 0 && s_n) s_base = atomicAdd(&g_z.cand_cnt[r], s_n);
    __syncthreads();
    for (unsigned i = threadIdx.x; i < s_n; i += TPB) g_cand[r][s_base + i] = s_keys[i];

    #pragma unroll
    for (int o = 16; o; o >>= 1) {
        psum += __shfl_down_sync(0xffffffffu, psum, o);
        pcnt += __shfl_down_sync(0xffffffffu, pcnt, o);
    }
    if (lane == 0 && pcnt) {
        atomicAdd(&g_z.pos_cnt[r], (unsigned)pcnt);
        atomicAdd(&g_z.pos_sum[r], psum);
    }
}

// ---------------- Fallback: only runs if cand_cnt < k ------------------------
static constexpr int FBX = 8;
__global__ void __launch_bounds__(TPB) pass_fb(const float* __restrict__ yp,
                                               const float* __restrict__ yt) {
    const int r = blockIdx.y;
    const unsigned aC = g_z.cand_cnt[r];             // stable: written only by pass_a
    if (aC >= kmin(g_z.pos_cnt[r])) return;          // common case: exit
    const unsigned lane = threadIdx.x & 31u;
    const size_t per = N / FBX;
    const size_t base = (size_t)r * N + (size_t)blockIdx.x * per;
    for (size_t e = (size_t)threadIdx.x * VEC; e < per; e += (size_t)TPB * VEC) {
        size_t idx = base + e;
        float4 p = *reinterpret_cast<const float4*>(yp + idx);
        float4 t = *reinterpret_cast<const float4*>(yt + idx);
        float pv[4] = {p.x, p.y, p.z, p.w};
        float tv[4] = {t.x, t.y, t.z, t.w};
        #pragma unroll
        for (int j = 0; j < 4; j++) {
            unsigned key = __float_as_uint(fabsf(pv[j]));
            bool take = (tv[j] == 0.f) && (key < CUT_BITS);
            unsigned bm = __ballot_sync(0xffffffffu, take);
            if (take) {
                unsigned leader = __ffs(bm) - 1u;
                unsigned pre = __popc(bm & ((1u << lane) - 1u));
                unsigned wbase;
                if (lane == leader) wbase = atomicAdd(&g_z.fb_cnt[r], (unsigned)__popc(bm));
                wbase = __shfl_sync(bm, wbase, leader);
                g_cand[r][aC + wbase + pre] = key;
            }
        }
    }
}

// ---------------- warp-0 suffix select over a shared histogram ---------------
// Finds b*: count(bins > b*) = cab < keff <= cab + h[b*]. Lanes 0..31 execute.
__device__ void warp_select(const unsigned* h, int nbins, unsigned keff,
                            int* out_b, unsigned* out_c) {
    const int lane = threadIdx.x;          // caller guarantees tid < 32
    const int chunk = nbins >> 5;
    unsigned cs = 0;
    for (int j = 0; j < chunk; j++) cs += h[lane * chunk + j];
    unsigned v = cs;
    #pragma unroll
    for (int off = 1; off < 32; off <<= 1) {
        unsigned g = __shfl_down_sync(0xffffffffu, v, off);
        if (lane + off < 32) v += g;
    }
    unsigned vnext = __shfl_down_sync(0xffffffffu, v, 1);
    if (lane == 31) vnext = 0u;
    bool hit = (v >= keff) && (vnext < keff);
    unsigned hb = __ballot_sync(0xffffffffu, hit);
    int c = __ffs(hb) - 1;
    unsigned S = __shfl_sync(0xffffffffu, vnext, c);   // count above chunk c
    for (int g = (chunk >> 5) - 1; g >= 0; g--) {
        unsigned hv = h[c * chunk + g * 32 + lane];
        unsigned w = hv;
        #pragma unroll
        for (int off = 1; off < 32; off <<= 1) {
            unsigned gg = __shfl_down_sync(0xffffffffu, w, off);
            if (lane + off < 32) w += gg;
        }
        unsigned wnext = __shfl_down_sync(0xffffffffu, w, 1);
        if (lane == 31) wnext = 0u;
        unsigned tot = __shfl_sync(0xffffffffu, w, 0);
        bool hit2 = (S + w >= keff) && (S + wnext < keff);
        unsigned hb2 = __ballot_sync(0xffffffffu, hit2);
        if (hb2) {
            int l = __ffs(hb2) - 1;
            unsigned wl = __shfl_sync(0xffffffffu, w, l);
            unsigned hl = __shfl_sync(0xffffffffu, hv, l);
            if (lane == 0) { *out_b = c * chunk + g * 32 + l; *out_c = S + wl - hl; }
            return;
        }
        S += tot;
    }
}

// ---------------- Pass E: exact select + neg sum -----------------------------
__global__ void __launch_bounds__(1024) pass_e() {
    const int r = blockIdx.x, tid = threadIdx.x;
    __shared__ unsigned sh[2048];          // h1 (1024) -> h2 (2048) -> h3c (1024)
    __shared__ float    h3s[1024];
    __shared__ int s_b; __shared__ unsigned s_c;
    __shared__ double d_sA, d_s2;

    const unsigned m = g_z.cand_cnt[r] + g_z.fb_cnt[r];
    const unsigned k = kmin(g_z.pos_cnt[r]);
    unsigned keff = (k > m) ? m : k;
    if (keff == 0u) { if (tid == 0) g_neg[r] = 0.0; return; }
    const unsigned* cand = g_cand[r];
    const unsigned lane = tid & 31u;

    // -- level 1 hist (key >> 21) --
    if (tid < 1024) sh[tid] = 0u;
    if (tid < 1024) sh[1024 + tid] = 0u;   // keep simple: zero 2048 anyway
    __syncthreads();
    {
        unsigned rounds = (m + 1023u) >> 10;
        for (unsigned t = 0; t < rounds; t++) {
            unsigned i = (t << 10) + tid;
            bool valid = i < m;
            unsigned msk = __ballot_sync(0xffffffffu, valid);
            if (valid) {
                unsigned b = cand[i] >> 21;
                unsigned mm = __match_any_sync(msk, b);
                if ((mm & ((1u << lane) - 1u)) == 0u)
                    atomicAdd(&sh[b], (unsigned)__popc(mm));
            }
        }
    }
    __syncthreads();
    if (tid < 32) warp_select(sh, 1024, keff, &s_b, &s_c);
    __syncthreads();
    const int b1 = s_b; const unsigned c1 = s_c;
    const unsigned kc1 = keff - c1;
    __syncthreads();

    // -- sweep 2: sum above b1; level-2 hist of ==b1 (bits [20:10]) --
    for (int i = tid; i < 2048; i += 1024) sh[i] = 0u;
    __syncthreads();
    double sA = 0.0;
    for (unsigned i = tid; i < m; i += 1024) {
        unsigned key = cand[i];
        int hb = (int)(key >> 21);
        if (hb > b1) sA += (double)fsl1(__uint_as_float(key));
        else if (hb == b1) atomicAdd(&sh[(key >> 10) & 0x7FFu], 1u);
    }
    sA = block_reduce_double(sA);
    if (tid == 0) d_sA = sA;
    __syncthreads();
    if (tid < 32) warp_select(sh, 2048, kc1, &s_b, &s_c);
    __syncthreads();
    const int b2 = s_b; const unsigned c2 = s_c;
    const unsigned kc2 = kc1 - c2;
    __syncthreads();

    // -- sweep 3: sum mid>b2; level-3 hist (cnt + fsum) of mid==b2 --
    if (tid < 1024) { sh[tid] = 0u; h3s[tid] = 0.f; }
    __syncthreads();
    double s2 = 0.0;
    for (unsigned i = tid; i < m; i += 1024) {
        unsigned key = cand[i];
        if ((int)(key >> 21) == b1) {
            int mid = (int)((key >> 10) & 0x7FFu);
            if (mid > b2) s2 += (double)fsl1(__uint_as_float(key));
            else if (mid == b2) {
                unsigned lo = key & 0x3FFu;
                atomicAdd(&sh[lo], 1u);
                atomicAdd(&h3s[lo], fsl1(__uint_as_float(key)));
            }
        }
    }
    s2 = block_reduce_double(s2);
    if (tid == 0) d_s2 = s2;
    __syncthreads();
    if (tid < 32) warp_select(sh, 1024, kc2, &s_b, &s_c);
    __syncthreads();
    const int b3 = s_b; const unsigned c3 = s_c;
    double s3 = (tid < 1024 && tid > b3) ? (double)h3s[tid] : 0.0;
    s3 = block_reduce_double(s3);
    if (tid == 0) {
        unsigned eq = kc2 - c3;
        unsigned thr = ((unsigned)b1 << 21) | ((unsigned)b2 << 10) | (unsigned)b3;
        float fT = fsl1(__uint_as_float(thr));
        g_neg[r] = d_sA + d_s2 + s3 + (double)eq * (double)fT;
    }
}

// ---------------- Pass F -----------------------------------------------------
__global__ void pass_f(float* __restrict__ out) {
    __shared__ double a[B], b[B], c[B], d[B];
    int tid = threadIdx.x;   // B threads
    a[tid] = g_z.pos_sum[tid];
    b[tid] = (double)g_z.pos_cnt[tid];
    c[tid] = g_neg[tid];
    d[tid] = (double)kmin(g_z.pos_cnt[tid]);
    __syncthreads();
    if (tid == 0) {
        double PS = 0, PC = 0, NS = 0, NC = 0;
        for (int i = 0; i < B; i++) { PS += a[i]; PC += b[i]; NS += c[i]; NC += d[i]; }
        double pos_loss = (PC > 0.0) ? PS / PC : 0.0;
        double neg_loss = (NC > 0.0) ? NS / NC : 0.0;
        out[0] = (float)((double)NEG_POS * pos_loss + neg_loss);
    }
}

// ---------------- launch ------------------------------------------------------
extern "C" void kernel_launch(void* const* d_in, const int* in_sizes, int n_in,
                              void* d_out, int out_size) {
    const float* yp = (const float*)d_in[0];
    const float* yt = (const float*)d_in[1];
    float* out = (float*)d_out;

    void* zp = nullptr;
    cudaGetSymbolAddress(&zp, g_z);
    cudaMemsetAsync(zp, 0, sizeof(Zeroed));

    dim3 grid(BPR, B);
    pass_a<<<grid, TPB>>>(yp, yt);
    pass_fb<<<dim3(FBX, B), TPB>>>(yp, yt);
    pass_e<<<B, 1024>>>();
    pass_f<<<1, B>>>(out);
}

// round 4
// speedup vs baseline: 3.1493x; 1.8313x over previous
#include <cuda_runtime.h>
#include <cuda_bf16.h>
#include <cstdint>

// OHEM smooth-L1 loss. y_pred,y_true: [64, 262144] fp32 -> scalar fp32.
//  pass A : single sweep; per-thread private staging of "interesting" (p,t)
//           pairs (pos OR |p|>=1.5625); phase-2 computes pos stats and a
//           counts-only 2048-bin histogram of big-negative |p| (keys 1.5625..6.25).
//  pass E : per-row top-k threshold from hist (bin-center approximation for the
//           unselected tail), rare exact-ish fallback, fused final scalar.

static constexpr int B = 64;
static constexpr int N = 256 * 256 * 4;        // 262144
static constexpr int NBINS = 2048;
static constexpr unsigned CUT_BITS = 0x3FC80000u;   // 1.5625f
static constexpr float   CUTF = 1.5625f;

struct Zeroed {
    unsigned hist[B][NBINS];   // big-neg counts, bin = (key-CUT)>>13 clamped
    unsigned pos_cnt[B];
    unsigned big_cnt[B];
    double   pos_sum[B];       // sum of smooth_l1 over positives
    double   big_suma[B];      // sum of a=|p| over all big negatives
    double   ns, nc;
    unsigned ticket;
};
__device__ Zeroed g_z;         // ~513 KB memset per launch

// valid in thread 0; internally barriered; all threads must call
__device__ double block_reduce_double(double v) {
    __shared__ double sh[32];
    int lane = threadIdx.x & 31, w = threadIdx.x >> 5;
    #pragma unroll
    for (int o = 16; o; o >>= 1) v += __shfl_down_sync(0xffffffffu, v, o);
    __syncthreads();
    if (lane == 0) sh[w] = v;
    __syncthreads();
    double r = 0.0;
    if (w == 0) {
        int nw = (blockDim.x + 31) >> 5;
        r = (lane < nw) ? sh[lane] : 0.0;
        #pragma unroll
        for (int o = 16; o; o >>= 1) r += __shfl_down_sync(0xffffffffu, r, o);
    }
    __syncthreads();
    return r;
}

__device__ __forceinline__ float fsl1(float a) {
    // smooth_l1 = 0.5*min(a,1)^2 - min(a,1) + a  (branch-free, exact)
    float u = fminf(a, 1.0f);
    return fmaf(u, fmaf(0.5f, u, -1.0f), a);
}
__device__ __forceinline__ float bin_center(int b) {
    return __uint_as_float(CUT_BITS + ((unsigned)b << 13) + (1u << 12));
}

// ---------------- Pass A -----------------------------------------------------
static constexpr int TPB = 256;
static constexpr int VEC = 4;
static constexpr int ITERS = 4;
static constexpr int EPB = TPB * VEC * ITERS;   // 4096
static constexpr int BPR = N / EPB;             // 64

__global__ void __launch_bounds__(TPB) pass_a(const float* __restrict__ yp,
                                              const float* __restrict__ yt) {
    __shared__ float2 sbuf[TPB][17];            // 16 slots + pad (bank-friendly)
    const int r = blockIdx.y;
    const size_t base = (size_t)r * N + (size_t)blockIdx.x * EPB;
    int cnt = 0;

    #pragma unroll
    for (int it = 0; it < ITERS; it++) {
        size_t idx = base + (size_t)it * (TPB * VEC) + (size_t)threadIdx.x * VEC;
        float4 p = *reinterpret_cast<const float4*>(yp + idx);
        float4 t = *reinterpret_cast<const float4*>(yt + idx);
        float pv[4] = {p.x, p.y, p.z, p.w};
        float tv[4] = {t.x, t.y, t.z, t.w};
        #pragma unroll
        for (int j = 0; j < 4; j++) {
            // t!=0 -> w huge; t==0 -> w=|p|.  interesting <=> w >= CUTF
            float w = fmaf(fabsf(tv[j]), 1e38f, fabsf(pv[j]));
            if (w >= CUTF) { sbuf[threadIdx.x][cnt] = make_float2(pv[j], tv[j]); cnt++; }
        }
    }

    // phase 2: process own staged entries (no sync needed; private slots)
    float psum = 0.f, bsum = 0.f; int pc = 0, bc = 0;
    for (int c = 0; c < cnt; c++) {
        float2 e = sbuf[threadIdx.x][c];
        if (e.y != 0.f) {                        // positive
            float a = fabsf(e.x - e.y);
            psum += fsl1(a);
            pc++;
        } else {                                 // big negative (|p| >= 1.5625)
            float a = fabsf(e.x);
            unsigned bin = (__float_as_uint(a) - CUT_BITS) >> 13;
            if (bin > (unsigned)(NBINS - 1)) bin = NBINS - 1;
            atomicAdd(&g_z.hist[r][bin], 1u);    // RED, fire-and-forget
            bsum += a; bc++;
        }
    }

    // block reduce the 4 scalars -> 4 global atomics per block
    double dps = block_reduce_double((double)psum);
    double dbs = block_reduce_double((double)bsum);
    double dpc = block_reduce_double((double)pc);
    double dbc = block_reduce_double((double)bc);
    if (threadIdx.x == 0) {
        if (dpc != 0.0) { atomicAdd(&g_z.pos_sum[r], dps); atomicAdd(&g_z.pos_cnt[r], (unsigned)(dpc + 0.5)); }
        if (dbc != 0.0) { atomicAdd(&g_z.big_suma[r], dbs); atomicAdd(&g_z.big_cnt[r], (unsigned)(dbc + 0.5)); }
    }
}

// ---------------- warp-0 suffix select over a shared histogram ---------------
// Finds b*: count(bins > b*) = c < keff <= c + h[b*]. Lanes 0..31 execute.
__device__ void warp_select(const unsigned* h, int nbins, unsigned keff,
                            int* out_b, unsigned* out_c) {
    const int lane = threadIdx.x;
    const int chunk = nbins >> 5;
    unsigned cs = 0;
    for (int j = 0; j < chunk; j++) cs += h[lane * chunk + j];
    unsigned v = cs;
    #pragma unroll
    for (int off = 1; off < 32; off <<= 1) {
        unsigned g = __shfl_down_sync(0xffffffffu, v, off);
        if (lane + off < 32) v += g;
    }
    unsigned vnext = __shfl_down_sync(0xffffffffu, v, 1);
    if (lane == 31) vnext = 0u;
    bool hit = (v >= keff) && (vnext < keff);
    unsigned hb = __ballot_sync(0xffffffffu, hit);
    int c = __ffs(hb) - 1;
    unsigned S = __shfl_sync(0xffffffffu, vnext, c);
    for (int g = (chunk >> 5) - 1; g >= 0; g--) {
        unsigned hv = h[c * chunk + g * 32 + lane];
        unsigned w = hv;
        #pragma unroll
        for (int off = 1; off < 32; off <<= 1) {
            unsigned gg = __shfl_down_sync(0xffffffffu, w, off);
            if (lane + off < 32) w += gg;
        }
        unsigned wnext = __shfl_down_sync(0xffffffffu, w, 1);
        if (lane == 31) wnext = 0u;
        unsigned tot = __shfl_sync(0xffffffffu, w, 0);
        bool hit2 = (S + w >= keff) && (S + wnext < keff);
        unsigned hb2 = __ballot_sync(0xffffffffu, hit2);
        if (hb2) {
            int l = __ffs(hb2) - 1;
            unsigned wl = __shfl_sync(0xffffffffu, w, l);
            unsigned hl = __shfl_sync(0xffffffffu, hv, l);
            if (lane == 0) { *out_b = c * chunk + g * 32 + l; *out_c = S + wl - hl; }
            return;
        }
        S += tot;
    }
}

// ---------------- Pass E: per-row finish + fused final scalar ----------------
__global__ void __launch_bounds__(256) pass_e(const float* __restrict__ yp,
                                              const float* __restrict__ yt,
                                              float* __restrict__ out) {
    const int r = blockIdx.x, tid = threadIdx.x;
    __shared__ unsigned s_h[NBINS];
    __shared__ float    s_f[NBINS];
    __shared__ int s_b; __shared__ unsigned s_c;
    __shared__ int s_last;

    for (int i = tid; i < NBINS; i += 256) s_h[i] = g_z.hist[r][i];
    __syncthreads();

    const unsigned pc = g_z.pos_cnt[r];
    const unsigned bc = g_z.big_cnt[r];
    const double   bsa = g_z.big_suma[r];
    unsigned k = 2u * pc; if (k > (unsigned)(N - 1)) k = (unsigned)(N - 1);
    const unsigned keff = (k < bc) ? k : bc;

    double negr = 0.0;                          // meaningful in tid 0 only
    if (keff > 0) {
        if (tid < 32) warp_select(s_h, NBINS, keff, &s_b, &s_c);
        __syncthreads();
        const int b1 = s_b; const unsigned cab = s_c;
        double unsel = 0.0;                     // sum-of-a over unselected bigs (approx)
        for (int b = tid; b < b1; b += 256)
            if (s_h[b]) unsel += (double)s_h[b] * (double)bin_center(b);
        unsel = block_reduce_double(unsel);
        if (tid == 0) {
            unsigned part_unsel = s_h[b1] - (keff - cab);
            unsel += (double)part_unsel * (double)bin_center(b1);
            negr = bsa - unsel - 0.5 * (double)keff;
        }
    }

    // rare fallback: k exceeds big count -> take top (k-bc) among below-cut negs
    if (bc < k) {
        __syncthreads();
        for (int i = tid; i < NBINS; i += 256) { s_h[i] = 0u; s_f[i] = 0.f; }
        __syncthreads();
        const size_t rb = (size_t)r * N;
        for (int i = tid; i < N; i += 256) {
            float p = yp[rb + i], t = yt[rb + i];
            if (t == 0.f) {
                float a = fabsf(p);
                if (a < CUTF) {
                    unsigned key = __float_as_uint(a);
                    unsigned bin = key >> 19; if (bin > (unsigned)(NBINS - 1)) bin = NBINS - 1;
                    atomicAdd(&s_h[bin], 1u);
                    atomicAdd(&s_f[bin], fsl1(a));
                }
            }
        }
        __syncthreads();
        unsigned tot = 0;
        {   double dt = 0.0;
            for (int i = tid; i < NBINS; i += 256) dt += (double)s_h[i];
            dt = block_reduce_double(dt);
            if (tid == 0) s_c = (unsigned)(dt + 0.5);
            __syncthreads();
            tot = s_c;
            __syncthreads();
        }
        unsigned kc = k - bc; if (kc > tot) kc = tot;
        if (kc > 0) {
            if (tid < 32) warp_select(s_h, NBINS, kc, &s_b, &s_c);
            __syncthreads();
            const int b1 = s_b; const unsigned cab = s_c;
            double ext = 0.0;
            for (int b = b1 + 1 + tid; b < NBINS; b += 256) ext += (double)s_f[b];
            ext = block_reduce_double(ext);
            if (tid == 0) {
                unsigned part = kc - cab;
                if (s_h[b1]) ext += (double)part * ((double)s_f[b1] / (double)s_h[b1]);
                negr += ext;
            }
        }
    }

    if (tid == 0) {
        atomicAdd(&g_z.ns, negr);
        atomicAdd(&g_z.nc, (double)k);
        __threadfence();
        s_last = (atomicAdd(&g_z.ticket, 1u) == (unsigned)(B - 1)) ? 1 : 0;
    }
    __syncthreads();
    if (s_last) {
        double ps = (tid < B) ? g_z.pos_sum[tid] : 0.0;
        double pcs = (tid < B) ? (double)g_z.pos_cnt[tid] : 0.0;
        ps = block_reduce_double(ps);
        pcs = block_reduce_double(pcs);
        if (tid == 0) {
            double NS = g_z.ns, NC = g_z.nc;
            double pos_loss = (pcs > 0.0) ? ps / pcs : 0.0;
            double neg_loss = (NC > 0.0) ? NS / NC : 0.0;
            out[0] = (float)(2.0 * pos_loss + neg_loss);
        }
    }
}

// ---------------- launch ------------------------------------------------------
extern "C" void kernel_launch(void* const* d_in, const int* in_sizes, int n_in,
                              void* d_out, int out_size) {
    const float* yp = (const float*)d_in[0];
    const float* yt = (const float*)d_in[1];
    float* out = (float*)d_out;

    void* zp = nullptr;
    cudaGetSymbolAddress(&zp, g_z);
    cudaMemsetAsync(zp, 0, sizeof(Zeroed));

    pass_a<<<dim3(BPR, B), TPB>>>(yp, yt);
    pass_e<<<B, 256>>>(yp, yt, out);
}